// round 12
// baseline (speedup 1.0000x reference)
#include <cuda_runtime.h>

// entmax-1.5 over rows. z = (mask? s : -1e4)*0.5; active iff z > rmax-1;
// tau = root of sum max((z-rmax)-tau,0)^2 = 1 in [-1,0];
// p = max(z-(rmax+tau),0)^2. Warp 0 runs 10 bisections on ~140 compacted
// actives + exact fixed-support closed form
//   tau = (S1 - sqrt(S1^2 - k(S2-1)))/k over support {v > lo}.
//
// R12: persistent CTAs (4/SM) with REGISTER prefetch. While row r is being
// reduced/solved/stored (memory-silent phases in R7), row r+stride's 8
// LDG.128 are already in flight into registers -> each CTA presents
// continuous DRAM demand. No zbuf: smem ~2KB, L1 shared traffic gone.

constexpr int COLS    = 4096;
constexpr int THREADS = 256;
constexpr int PER     = COLS / THREADS;  // 16
constexpr int VEC     = PER / 4;         // 4
constexpr int NWARP   = THREADS / 32;    // 8
constexpr int NB      = 10;
constexpr int CAP     = 128;             // warp-0 register fast path (4/lane)
constexpr int ACAP    = 512;
constexpr int CTAS    = 592;             // 148 SMs * 4 CTAs

__device__ __forceinline__ float warp_sum(float v) {
#pragma unroll
    for (int off = 16; off > 0; off >>= 1)
        v += __shfl_xor_sync(0xffffffffu, v, off);
    return v;
}

__global__ __launch_bounds__(THREADS, 4) void entmax15_kernel(
    const float* __restrict__ scores,
    const int* __restrict__ mask,
    float* __restrict__ out,
    int rows)
{
    __shared__ float abuf[ACAP];         // compacted actives (v = z - rmax)
    __shared__ float sh_max[NWARP];
    __shared__ float sh_red[2][NWARP];   // fallback block reduction
    __shared__ float sh_taup;
    __shared__ int   cnt;

    const int t    = threadIdx.x;
    const int wid  = t >> 5;
    const int lane = t & 31;
    const int stride = gridDim.x;
    const size_t rowstep = (size_t)stride * COLS;

    if (t == 0) cnt = 0;
    __syncthreads();

    // ---- Prologue: prefetch first row into registers ----
    float4 ps[VEC];
    int4   pm[VEC];
    int r = blockIdx.x;
    const float* sp = scores + (size_t)r * COLS;
    const int*   mp = mask   + (size_t)r * COLS;
    float*       op = out    + (size_t)r * COLS;
    if (r < rows) {
#pragma unroll
        for (int c = 0; c < VEC; ++c) {
            const int idx = c * (THREADS * 4) + t * 4;
            ps[c] = __ldcs(reinterpret_cast<const float4*>(sp + idx));
            pm[c] = __ldcs(reinterpret_cast<const int4*>(mp + idx));
        }
    }

    for (; r < rows; r += stride) {
        // ---- Convert prefetched regs -> z; warp-local max ----
        float z[PER];
        float lmax = -3.402823e38f;
#pragma unroll
        for (int c = 0; c < VEC; ++c) {
            float z0 = (pm[c].x ? ps[c].x : -1.0e4f) * 0.5f;
            float z1 = (pm[c].y ? ps[c].y : -1.0e4f) * 0.5f;
            float z2 = (pm[c].z ? ps[c].z : -1.0e4f) * 0.5f;
            float z3 = (pm[c].w ? ps[c].w : -1.0e4f) * 0.5f;
            z[c*4+0] = z0; z[c*4+1] = z1; z[c*4+2] = z2; z[c*4+3] = z3;
            lmax = fmaxf(lmax, fmaxf(fmaxf(z0, z1), fmaxf(z2, z3)));
        }

        // ---- Issue next row's prefetch NOW (streams during solve/store) ----
        const int rn = r + stride;
        sp += rowstep; mp += rowstep;
        if (rn < rows) {
#pragma unroll
            for (int c = 0; c < VEC; ++c) {
                const int idx = c * (THREADS * 4) + t * 4;
                ps[c] = __ldcs(reinterpret_cast<const float4*>(sp + idx));
                pm[c] = __ldcs(reinterpret_cast<const int4*>(mp + idx));
            }
        }

        // ---- Block max ----
#pragma unroll
        for (int off = 16; off > 0; off >>= 1)
            lmax = fmaxf(lmax, __shfl_xor_sync(0xffffffffu, lmax, off));
        if (lane == 0) sh_max[wid] = lmax;
        __syncthreads();                       // cnt=0 also visible (set below prev iter / prologue)
        float rmax = sh_max[0];
#pragma unroll
        for (int i = 1; i < NWARP; ++i) rmax = fmaxf(rmax, sh_max[i]);
        const float thr = rmax - 1.0f;

        // ---- Compact actives from registers (store v = z - rmax) ----
#pragma unroll
        for (int i = 0; i < PER; ++i) {
            if (z[i] > thr) {
                int p = atomicAdd(&cnt, 1);    // warp-aggregated
                if (p < ACAP) abuf[p] = z[i] - rmax;
            }
        }
        __syncthreads();
        const int n = cnt;                     // uniform across block

        if (n <= ACAP) {
            // ---- Warp 0 solves tau; others proceed to barrier ----
            if (wid == 0) {
                float lo = -1.0f, hi = 0.0f;
                float tau;
                if (n <= CAP) {
                    float v[4];
#pragma unroll
                    for (int j = 0; j < 4; ++j) {
                        int i = lane + 32 * j;
                        v[j] = (i < n) ? abuf[i] : -2.0f;   // sentinel
                    }
#pragma unroll 1
                    for (int it = 0; it < NB; ++it) {
                        const float tm = 0.5f * (lo + hi);
                        float acc = 0.0f;
#pragma unroll
                        for (int j = 0; j < 4; ++j) {
                            float d = fmaxf(v[j] - tm, 0.0f);
                            acc = fmaf(d, d, acc);
                        }
                        if (warp_sum(acc) >= 1.0f) lo = tm; else hi = tm;
                    }
                    float k = 0.0f, S1 = 0.0f, S2 = 0.0f;
#pragma unroll
                    for (int j = 0; j < 4; ++j)
                        if (v[j] > lo) { k += 1.0f; S1 += v[j]; S2 = fmaf(v[j], v[j], S2); }
                    k = warp_sum(k); S1 = warp_sum(S1); S2 = warp_sum(S2);
                    float disc = fmaxf(fmaf(S1, S1, -k * (S2 - 1.0f)), 0.0f);
                    tau = (S1 - sqrtf(disc)) / k;
                } else {
#pragma unroll 1
                    for (int it = 0; it < NB; ++it) {
                        const float tm = 0.5f * (lo + hi);
                        float acc = 0.0f;
                        for (int i = lane; i < n; i += 32) {
                            float d = fmaxf(abuf[i] - tm, 0.0f);
                            acc = fmaf(d, d, acc);
                        }
                        if (warp_sum(acc) >= 1.0f) lo = tm; else hi = tm;
                    }
                    float k = 0.0f, S1 = 0.0f, S2 = 0.0f;
                    for (int i = lane; i < n; i += 32) {
                        float v = abuf[i];
                        if (v > lo) { k += 1.0f; S1 += v; S2 = fmaf(v, v, S2); }
                    }
                    k = warp_sum(k); S1 = warp_sum(S1); S2 = warp_sum(S2);
                    float disc = fmaxf(fmaf(S1, S1, -k * (S2 - 1.0f)), 0.0f);
                    tau = (S1 - sqrtf(disc)) / k;
                }
                if (lane == 0) sh_taup = tau + rmax;
            }
        } else {
            // ---- Pathological (n > ACAP): block-parallel deep bisection ----
            float lo = -1.0f, hi = 0.0f;
#pragma unroll 1
            for (int it = 0; it < 30; ++it) {
                const float tm = 0.5f * (lo + hi);
                float acc = 0.0f;
#pragma unroll
                for (int i = 0; i < PER; ++i) {
                    float d = fmaxf((z[i] - rmax) - tm, 0.0f);
                    acc = fmaf(d, d, acc);
                }
                acc = warp_sum(acc);
                const int b = it & 1;
                if (lane == 0) sh_red[b][wid] = acc;
                __syncthreads();
                float tot = sh_red[b][0];
#pragma unroll
                for (int i = 1; i < NWARP; ++i) tot += sh_red[b][i];
                if (tot >= 1.0f) lo = tm; else hi = tm;
            }
            if (t == 0) sh_taup = 0.5f * (lo + hi) + rmax;
        }

        if (t == 0) cnt = 0;                   // reset for next iteration
        __syncthreads();
        const float taup = sh_taup;            // p = max(z - taup, 0)^2

        // ---- Store from registers ----
#pragma unroll
        for (int c = 0; c < VEC; ++c) {
            const int idx = c * (THREADS * 4) + t * 4;
            float d0 = fmaxf(z[c*4+0] - taup, 0.0f);
            float d1 = fmaxf(z[c*4+1] - taup, 0.0f);
            float d2 = fmaxf(z[c*4+2] - taup, 0.0f);
            float d3 = fmaxf(z[c*4+3] - taup, 0.0f);
            float4 p;
            p.x = d0*d0; p.y = d1*d1; p.z = d2*d2; p.w = d3*d3;
            __stcs(reinterpret_cast<float4*>(op + idx), p);
        }
        op += rowstep;
    }
}

extern "C" void kernel_launch(void* const* d_in, const int* in_sizes, int n_in,
                              void* d_out, int out_size) {
    const float* scores = (const float*)d_in[0];
    const int*   mask   = (const int*)d_in[1];
    float* out = (float*)d_out;
    const int rows = in_sizes[0] / COLS;
    const int grid = rows < CTAS ? rows : CTAS;
    entmax15_kernel<<<grid, THREADS>>>(scores, mask, out, rows);
}

// round 13
// speedup vs baseline: 1.1219x; 1.1219x over previous
#include <cuda_runtime.h>
#include <cstdint>

// entmax-1.5 over rows. z = (mask? s : -1e4)*0.5; active iff z > rmax-1;
// tau = root of sum max((z-rmax)-tau,0)^2 = 1 in [-1,0]; p = max(z-(rmax+tau),0)^2.
// Warp 0: 10 bisections over ~140 compacted actives + exact fixed-support
// closed form tau = (S1 - sqrt(S1^2 - k(S2-1)))/k over {v > lo}.
//
// R13 overlap: persistent CTAs (5/SM). Row r+stride's raw scores+mask stream
// into a single 32KB smem stage via cp.async.cg WHILE row r's compact/solve/
// store run. z lives in registers (51-reg budget at 5 CTAs; no zbuf, no
// spills). Each thread converts only its own stage slice right after
// wait_group (self-ordered), so the stage is reusable at the first barrier.

constexpr int COLS    = 4096;
constexpr int THREADS = 256;
constexpr int PER     = COLS / THREADS;  // 16
constexpr int VEC     = PER / 4;         // 4
constexpr int NWARP   = THREADS / 32;    // 8
constexpr int NB      = 10;
constexpr int CAP     = 128;             // warp-0 register fast path (4/lane)
constexpr int ACAP    = 512;
constexpr int OCC     = 5;
constexpr int CTAS    = 148 * OCC;       // 740
constexpr int DYN_SMEM = COLS * 4 * 2;   // stage: scores f32 + mask i32 = 32KB

__device__ __forceinline__ void cp_async16(void* dst_smem, const void* src_g) {
    uint32_t s = (uint32_t)__cvta_generic_to_shared(dst_smem);
    asm volatile("cp.async.cg.shared.global [%0], [%1], 16;\n" :: "r"(s), "l"(src_g));
}
__device__ __forceinline__ void cp_commit() {
    asm volatile("cp.async.commit_group;\n" ::: "memory");
}
__device__ __forceinline__ void cp_wait0() {
    asm volatile("cp.async.wait_group 0;\n" ::: "memory");
}

__device__ __forceinline__ float warp_sum(float v) {
#pragma unroll
    for (int off = 16; off > 0; off >>= 1)
        v += __shfl_xor_sync(0xffffffffu, v, off);
    return v;
}

__global__ __launch_bounds__(THREADS, OCC) void entmax15_kernel(
    const float* __restrict__ scores,
    const int* __restrict__ mask,
    float* __restrict__ out,
    int rows)
{
    extern __shared__ char smraw[];
    float* s_sc = reinterpret_cast<float*>(smraw);            // [COLS]
    int*   s_mk = reinterpret_cast<int*>(smraw + COLS * 4);   // [COLS]

    __shared__ float abuf[ACAP];         // compacted actives (v = z - rmax)
    __shared__ float sh_max[NWARP];
    __shared__ float sh_red[2][NWARP];   // pathological fallback
    __shared__ float sh_taup;
    __shared__ int   cnt;

    const int t    = threadIdx.x;
    const int wid  = t >> 5;
    const int lane = t & 31;
    const int stride = gridDim.x;

    if (t == 0) cnt = 0;                 // visible via B1 before first atomics

    // ---- Prologue: prefetch first row into the stage ----
    int r = blockIdx.x;
    if (r < rows) {
        const float* gs = scores + (size_t)r * COLS;
        const int*   gm = mask   + (size_t)r * COLS;
#pragma unroll
        for (int c = 0; c < VEC; ++c) {
            const int idx = c * (THREADS * 4) + t * 4;
            cp_async16(s_sc + idx, gs + idx);
            cp_async16(s_mk + idx, gm + idx);
        }
    }
    cp_commit();

    for (; r < rows; r += stride) {
        // ---- Wait own prefetch; convert own slice -> z regs; warp max ----
        cp_wait0();      // this thread's copies done; it reads only its slice
        float z[PER];
        float lmax = -3.402823e38f;
#pragma unroll
        for (int c = 0; c < VEC; ++c) {
            const int idx = c * (THREADS * 4) + t * 4;
            float4 v  = *reinterpret_cast<const float4*>(s_sc + idx);
            int4   mm = *reinterpret_cast<const int4*>(s_mk + idx);
            float z0 = (mm.x ? v.x : -1.0e4f) * 0.5f;
            float z1 = (mm.y ? v.y : -1.0e4f) * 0.5f;
            float z2 = (mm.z ? v.z : -1.0e4f) * 0.5f;
            float z3 = (mm.w ? v.w : -1.0e4f) * 0.5f;
            z[c*4+0] = z0; z[c*4+1] = z1; z[c*4+2] = z2; z[c*4+3] = z3;
            lmax = fmaxf(lmax, fmaxf(fmaxf(z0, z1), fmaxf(z2, z3)));
        }
#pragma unroll
        for (int off = 16; off > 0; off >>= 1)
            lmax = fmaxf(lmax, __shfl_xor_sync(0xffffffffu, lmax, off));
        if (lane == 0) sh_max[wid] = lmax;

        __syncthreads();   // B1: sh_max ready; every thread done with stage

        float rmax = sh_max[0];
#pragma unroll
        for (int i = 1; i < NWARP; ++i) rmax = fmaxf(rmax, sh_max[i]);
        const float thr = rmax - 1.0f;

        // ---- Issue next row's prefetch NOW: streams through compact/solve/store
        const int rn = r + stride;
        if (rn < rows) {
            const float* gs = scores + (size_t)rn * COLS;
            const int*   gm = mask   + (size_t)rn * COLS;
#pragma unroll
            for (int c = 0; c < VEC; ++c) {
                const int idx = c * (THREADS * 4) + t * 4;
                cp_async16(s_sc + idx, gs + idx);
                cp_async16(s_mk + idx, gm + idx);
            }
        }
        cp_commit();       // (possibly empty group; wait0 stays valid)

        // ---- Compact actives from regs (store v = z - rmax) ----
#pragma unroll
        for (int i = 0; i < PER; ++i) {
            if (z[i] > thr) {
                int p = atomicAdd(&cnt, 1);      // warp-aggregated
                if (p < ACAP) abuf[p] = z[i] - rmax;
            }
        }
        __syncthreads();   // B2
        const int n = cnt; // uniform

        if (n >= 1 && n <= ACAP) {
            if (wid == 0) {
                float lo = -1.0f, hi = 0.0f;
                float tau;
                if (n <= CAP) {
                    float v[4];
#pragma unroll
                    for (int j = 0; j < 4; ++j) {
                        int i = lane + 32 * j;
                        v[j] = (i < n) ? abuf[i] : -2.0f;   // sentinel
                    }
#pragma unroll 1
                    for (int it = 0; it < NB; ++it) {
                        const float tm = 0.5f * (lo + hi);
                        float acc = 0.0f;
#pragma unroll
                        for (int j = 0; j < 4; ++j) {
                            float d = fmaxf(v[j] - tm, 0.0f);
                            acc = fmaf(d, d, acc);
                        }
                        if (warp_sum(acc) >= 1.0f) lo = tm; else hi = tm;
                    }
                    float k = 0.0f, S1 = 0.0f, S2 = 0.0f;
#pragma unroll
                    for (int j = 0; j < 4; ++j)
                        if (v[j] > lo) { k += 1.0f; S1 += v[j]; S2 = fmaf(v[j], v[j], S2); }
                    k = warp_sum(k); S1 = warp_sum(S1); S2 = warp_sum(S2);
                    float disc = fmaxf(fmaf(S1, S1, -k * (S2 - 1.0f)), 0.0f);
                    tau = (S1 - sqrtf(disc)) / k;
                } else {
#pragma unroll 1
                    for (int it = 0; it < NB; ++it) {
                        const float tm = 0.5f * (lo + hi);
                        float acc = 0.0f;
                        for (int i = lane; i < n; i += 32) {
                            float d = fmaxf(abuf[i] - tm, 0.0f);
                            acc = fmaf(d, d, acc);
                        }
                        if (warp_sum(acc) >= 1.0f) lo = tm; else hi = tm;
                    }
                    float k = 0.0f, S1 = 0.0f, S2 = 0.0f;
                    for (int i = lane; i < n; i += 32) {
                        float v = abuf[i];
                        if (v > lo) { k += 1.0f; S1 += v; S2 = fmaf(v, v, S2); }
                    }
                    k = warp_sum(k); S1 = warp_sum(S1); S2 = warp_sum(S2);
                    float disc = fmaxf(fmaf(S1, S1, -k * (S2 - 1.0f)), 0.0f);
                    tau = (S1 - sqrtf(disc)) / k;
                }
                if (lane == 0) sh_taup = tau + rmax;
            }
        } else {
            // ---- Pathological (n==0 overflow-masked or n>ACAP): block bisection
            float lo = -1.0f, hi = 0.0f;
#pragma unroll 1
            for (int it = 0; it < 30; ++it) {
                const float tm = 0.5f * (lo + hi);
                float acc = 0.0f;
#pragma unroll
                for (int i = 0; i < PER; ++i) {
                    float d = fmaxf((z[i] - rmax) - tm, 0.0f);
                    acc = fmaf(d, d, acc);
                }
                acc = warp_sum(acc);
                const int b = it & 1;
                if (lane == 0) sh_red[b][wid] = acc;
                __syncthreads();
                float tot = sh_red[b][0];
#pragma unroll
                for (int i = 1; i < NWARP; ++i) tot += sh_red[b][i];
                if (tot >= 1.0f) lo = tm; else hi = tm;
            }
            if (t == 0) sh_taup = 0.5f * (lo + hi) + rmax;
        }

        if (t == 0) cnt = 0;     // reset for next row (ordered by B3)
        __syncthreads();         // B3
        const float taup = sh_taup;

        // ---- Store p = max(z - taup, 0)^2 from regs ----
        float* o = out + (size_t)r * COLS;
#pragma unroll
        for (int c = 0; c < VEC; ++c) {
            const int idx = c * (THREADS * 4) + t * 4;
            float d0 = fmaxf(z[c*4+0] - taup, 0.0f);
            float d1 = fmaxf(z[c*4+1] - taup, 0.0f);
            float d2 = fmaxf(z[c*4+2] - taup, 0.0f);
            float d3 = fmaxf(z[c*4+3] - taup, 0.0f);
            float4 p;
            p.x = d0*d0; p.y = d1*d1; p.z = d2*d2; p.w = d3*d3;
            __stcs(reinterpret_cast<float4*>(o + idx), p);
        }
    }
}

extern "C" void kernel_launch(void* const* d_in, const int* in_sizes, int n_in,
                              void* d_out, int out_size) {
    const float* scores = (const float*)d_in[0];
    const int*   mask   = (const int*)d_in[1];
    float* out = (float*)d_out;
    const int rows = in_sizes[0] / COLS;
    cudaFuncSetAttribute(entmax15_kernel,
                         cudaFuncAttributeMaxDynamicSharedMemorySize, DYN_SMEM);
    const int grid = rows < CTAS ? rows : CTAS;
    entmax15_kernel<<<grid, THREADS, DYN_SMEM>>>(scores, mask, out, rows);
}

// round 14
// speedup vs baseline: 1.3031x; 1.1615x over previous
#include <cuda_runtime.h>

// entmax-1.5 over rows. zbuf = (mask? s : -1e4)*0.5 (unshifted) in shared.
// tau = root of sum max((z-rmax)-tau,0)^2 = 1 in [-1,0]; p = max(z-(rmax+tau),0)^2.
//
// R14 = R7 with the global-max barrier removed: compaction uses the WARP-local
// threshold (wmax-1 >= rmax-1 admits every true active; superset elements have
// v <= -1, contribute 0 in all bisection steps, and are excluded by the closed
// form's support test v > lo). Each warp compacts its own just-written zbuf
// slice -> no barrier between load and compact. Two rendezvous per row.

constexpr int COLS    = 4096;
constexpr int THREADS = 256;
constexpr int PER     = COLS / THREADS;  // 16
constexpr int VEC     = PER / 4;         // 4
constexpr int NWARP   = THREADS / 32;    // 8
constexpr int NB      = 10;
constexpr int CAP     = 128;             // warp-0 register fast path (4/lane)
constexpr int ACAP    = 768;             // superset capacity (~380 typical)

__device__ __forceinline__ float warp_sum(float v) {
#pragma unroll
    for (int off = 16; off > 0; off >>= 1)
        v += __shfl_xor_sync(0xffffffffu, v, off);
    return v;
}

__global__ __launch_bounds__(THREADS, 8) void entmax15_kernel(
    const float* __restrict__ scores,
    const int* __restrict__ mask,
    float* __restrict__ out)
{
    __shared__ float zbuf[COLS];         // full row of z (unshifted)
    __shared__ float abuf[ACAP];         // warp-threshold superset (raw z)
    __shared__ float sh_max[NWARP];
    __shared__ float sh_red[2][NWARP];   // pathological fallback reduction
    __shared__ float sh_taup;
    __shared__ int   cnt;

    const size_t row = blockIdx.x;
    const float* s = scores + row * COLS;
    const int*   m = mask   + row * COLS;
    float* o = out + row * COLS;

    const int t    = threadIdx.x;
    const int wid  = t >> 5;
    const int lane = t & 31;

    // B0: order cnt=0 before any atomicAdd. Cheap — all warps at kernel start.
    if (t == 0) cnt = 0;
    __syncthreads();

    // ---- Load, mask, *0.5 -> shared; warp-local max ----
    float lmax = -3.402823e38f;
#pragma unroll
    for (int c = 0; c < VEC; ++c) {
        const int idx = c * (THREADS * 4) + t * 4;
        float4 v  = __ldcs(reinterpret_cast<const float4*>(s + idx));
        int4   mm = __ldcs(reinterpret_cast<const int4*>(m + idx));
        float4 zz;
        zz.x = (mm.x ? v.x : -1.0e4f) * 0.5f;
        zz.y = (mm.y ? v.y : -1.0e4f) * 0.5f;
        zz.z = (mm.z ? v.z : -1.0e4f) * 0.5f;
        zz.w = (mm.w ? v.w : -1.0e4f) * 0.5f;
        *reinterpret_cast<float4*>(zbuf + idx) = zz;
        lmax = fmaxf(lmax, fmaxf(fmaxf(zz.x, zz.y), fmaxf(zz.z, zz.w)));
    }

    // ---- Warp max (no block barrier needed before compaction) ----
#pragma unroll
    for (int off = 16; off > 0; off >>= 1)
        lmax = fmaxf(lmax, __shfl_xor_sync(0xffffffffu, lmax, off));
    if (lane == 0) sh_max[wid] = lmax;

    // ---- Warp-threshold compaction from OWN zbuf slice (self-consistent) ----
    // wthr floor -4000 rejects fully-masked warp slices (fill z = -5000).
    const float wthr = fmaxf(lmax - 1.0f, -4000.0f);
#pragma unroll
    for (int c = 0; c < VEC; ++c) {
        const int idx = c * (THREADS * 4) + t * 4;
        float4 zz = *reinterpret_cast<const float4*>(zbuf + idx);
#pragma unroll
        for (int j = 0; j < 4; ++j) {
            float zv = (&zz.x)[j];
            if (zv > wthr) {
                int p = atomicAdd(&cnt, 1);      // warp-aggregated
                if (p < ACAP) abuf[p] = zv;      // raw (unshifted) z
            }
        }
    }

    __syncthreads();   // B1: sh_max, abuf, cnt all published

    const int n = cnt;

    if (n >= 1 && n <= ACAP) {
        // ---- Warp 0 solves tau; warps 1-7 run to B2 ----
        if (wid == 0) {
            float rmax = sh_max[0];
#pragma unroll
            for (int i = 1; i < NWARP; ++i) rmax = fmaxf(rmax, sh_max[i]);

            float lo = -1.0f, hi = 0.0f;
            float tau;
            if (n <= CAP) {
                float v[4];
#pragma unroll
                for (int j = 0; j < 4; ++j) {
                    int i = lane + 32 * j;
                    v[j] = (i < n) ? (abuf[i] - rmax) : -2.0f;   // sentinel
                }
#pragma unroll 1
                for (int it = 0; it < NB; ++it) {
                    const float tm = 0.5f * (lo + hi);
                    float acc = 0.0f;
#pragma unroll
                    for (int j = 0; j < 4; ++j) {
                        float d = fmaxf(v[j] - tm, 0.0f);
                        acc = fmaf(d, d, acc);
                    }
                    if (warp_sum(acc) >= 1.0f) lo = tm; else hi = tm;
                }
                float k = 0.0f, S1 = 0.0f, S2 = 0.0f;
#pragma unroll
                for (int j = 0; j < 4; ++j)
                    if (v[j] > lo) { k += 1.0f; S1 += v[j]; S2 = fmaf(v[j], v[j], S2); }
                k = warp_sum(k); S1 = warp_sum(S1); S2 = warp_sum(S2);
                float disc = fmaxf(fmaf(S1, S1, -k * (S2 - 1.0f)), 0.0f);
                tau = (S1 - sqrtf(disc)) / k;
            } else {
#pragma unroll 1
                for (int it = 0; it < NB; ++it) {
                    const float tm = 0.5f * (lo + hi);
                    float acc = 0.0f;
                    for (int i = lane; i < n; i += 32) {
                        float d = fmaxf((abuf[i] - rmax) - tm, 0.0f);
                        acc = fmaf(d, d, acc);
                    }
                    if (warp_sum(acc) >= 1.0f) lo = tm; else hi = tm;
                }
                float k = 0.0f, S1 = 0.0f, S2 = 0.0f;
                for (int i = lane; i < n; i += 32) {
                    float v = abuf[i] - rmax;
                    if (v > lo) { k += 1.0f; S1 += v; S2 = fmaf(v, v, S2); }
                }
                k = warp_sum(k); S1 = warp_sum(S1); S2 = warp_sum(S2);
                float disc = fmaxf(fmaf(S1, S1, -k * (S2 - 1.0f)), 0.0f);
                tau = (S1 - sqrtf(disc)) / k;
            }
            if (lane == 0) sh_taup = tau + rmax;
        }
    } else {
        // ---- Pathological (n == 0 all-masked, or n > ACAP): block bisection ----
        float rmax = sh_max[0];
#pragma unroll
        for (int i = 1; i < NWARP; ++i) rmax = fmaxf(rmax, sh_max[i]);
        float lo = -1.0f, hi = 0.0f;
#pragma unroll 1
        for (int it = 0; it < 30; ++it) {
            const float tm = 0.5f * (lo + hi);
            float acc = 0.0f;
#pragma unroll
            for (int c = 0; c < VEC; ++c) {
                const int idx = c * (THREADS * 4) + t * 4;
                float4 zz = *reinterpret_cast<const float4*>(zbuf + idx);
#pragma unroll
                for (int j = 0; j < 4; ++j) {
                    float d = fmaxf(((&zz.x)[j] - rmax) - tm, 0.0f);
                    acc = fmaf(d, d, acc);
                }
            }
            acc = warp_sum(acc);
            const int b = it & 1;
            if (lane == 0) sh_red[b][wid] = acc;
            __syncthreads();
            float tot = sh_red[b][0];
#pragma unroll
            for (int i = 1; i < NWARP; ++i) tot += sh_red[b][i];
            if (tot >= 1.0f) lo = tm; else hi = tm;
        }
        if (t == 0) sh_taup = 0.5f * (lo + hi) + rmax;
    }

    __syncthreads();   // B2: sh_taup published
    const float taup = sh_taup;   // p = max(z - taup, 0)^2

    // ---- Store p from shared ----
#pragma unroll
    for (int c = 0; c < VEC; ++c) {
        const int idx = c * (THREADS * 4) + t * 4;
        float4 zz = *reinterpret_cast<const float4*>(zbuf + idx);
        float d0 = fmaxf(zz.x - taup, 0.0f);
        float d1 = fmaxf(zz.y - taup, 0.0f);
        float d2 = fmaxf(zz.z - taup, 0.0f);
        float d3 = fmaxf(zz.w - taup, 0.0f);
        float4 p;
        p.x = d0*d0; p.y = d1*d1; p.z = d2*d2; p.w = d3*d3;
        __stcs(reinterpret_cast<float4*>(o + idx), p);
    }
}

extern "C" void kernel_launch(void* const* d_in, const int* in_sizes, int n_in,
                              void* d_out, int out_size) {
    const float* scores = (const float*)d_in[0];
    const int*   mask   = (const int*)d_in[1];
    float* out = (float*)d_out;
    const int rows = in_sizes[0] / COLS;
    entmax15_kernel<<<rows, THREADS>>>(scores, mask, out);
}

// round 15
// speedup vs baseline: 1.4942x; 1.1466x over previous
#include <cuda_runtime.h>

// entmax-1.5 over rows. zbuf holds z = (mask? s : -1e4)*0.5 (unshifted) in shared;
// active iff z > rmax-1; tau = root of sum max((z-rmax)-tau,0)^2 = 1 in [-1,0];
// p = max(z-(rmax+tau),0)^2. ~140/4096 elements active; warp 0 runs 10
// bisections on register-resident actives + exact fixed-support closed form
//   tau = (S1 - sqrt(S1^2 - k(S2-1)))/k  over support {v > lo}.
//
// R15 = R7 + per-thread compact skip: each thread keeps its private
// 16-element max (tmax) from the load phase; after the global max barrier,
// threads with tmax <= rmax-1 provably own no actives and skip the entire
// compact re-read (4 LDS.128 + 16 compares). ~58% of threads skip.

constexpr int COLS    = 4096;
constexpr int THREADS = 256;
constexpr int PER     = COLS / THREADS;  // 16
constexpr int VEC     = PER / 4;         // 4
constexpr int NWARP   = THREADS / 32;    // 8
constexpr int NB      = 10;              // bisection iterations
constexpr int CAP     = 128;             // register fast path (4/lane)
constexpr int ACAP    = 1024;            // abuf capacity (mid path)

__device__ __forceinline__ float warp_sum(float v) {
#pragma unroll
    for (int off = 16; off > 0; off >>= 1)
        v += __shfl_xor_sync(0xffffffffu, v, off);
    return v;
}

__global__ __launch_bounds__(THREADS, 8) void entmax15_kernel(
    const float* __restrict__ scores,
    const int* __restrict__ mask,
    float* __restrict__ out)
{
    __shared__ float zbuf[COLS];     // full row of z (unshifted)
    __shared__ float abuf[ACAP];     // compacted actives (shifted: v = z - rmax)
    __shared__ float sh_max[NWARP];
    __shared__ float sh_tau;
    __shared__ int   cnt;

    const size_t row = blockIdx.x;
    const float* s = scores + row * COLS;
    const int*   m = mask   + row * COLS;
    float* o = out + row * COLS;

    const int t    = threadIdx.x;
    const int wid  = t >> 5;
    const int lane = t & 31;

    // ---- Load, mask, *0.5 -> shared; track local max ----
    float lmax = -3.402823e38f;
#pragma unroll
    for (int c = 0; c < VEC; ++c) {
        const int idx = c * (THREADS * 4) + t * 4;
        float4 v  = __ldcs(reinterpret_cast<const float4*>(s + idx));
        int4   mm = __ldcs(reinterpret_cast<const int4*>(m + idx));
        float4 zz;
        zz.x = (mm.x ? v.x : -1.0e4f) * 0.5f;
        zz.y = (mm.y ? v.y : -1.0e4f) * 0.5f;
        zz.z = (mm.z ? v.z : -1.0e4f) * 0.5f;
        zz.w = (mm.w ? v.w : -1.0e4f) * 0.5f;
        *reinterpret_cast<float4*>(zbuf + idx) = zz;
        lmax = fmaxf(lmax, fmaxf(fmaxf(zz.x, zz.y), fmaxf(zz.z, zz.w)));
    }
    const float tmax = lmax;         // private 16-element max (skip test)

    // ---- Block max ----
#pragma unroll
    for (int off = 16; off > 0; off >>= 1)
        lmax = fmaxf(lmax, __shfl_xor_sync(0xffffffffu, lmax, off));
    if (lane == 0) sh_max[wid] = lmax;
    if (t == 0) cnt = 0;
    __syncthreads();
    float rmax = sh_max[0];
#pragma unroll
    for (int i = 1; i < NWARP; ++i) rmax = fmaxf(rmax, sh_max[i]);
    const float thr = rmax - 1.0f;   // active iff z > thr

    // ---- Compact actives from shared (store shifted v = z - rmax) ----
    // Skip entirely if this thread's slice max can't exceed the threshold.
    if (tmax > thr) {
#pragma unroll
        for (int c = 0; c < VEC; ++c) {
            const int idx = c * (THREADS * 4) + t * 4;
            float4 zz = *reinterpret_cast<const float4*>(zbuf + idx);
#pragma unroll
            for (int j = 0; j < 4; ++j) {
                float zv = (&zz.x)[j];
                if (zv > thr) {
                    int p = atomicAdd(&cnt, 1);          // warp-aggregated
                    if (p < ACAP) abuf[p] = zv - rmax;
                }
            }
        }
    }
    __syncthreads();

    // ---- Warp 0 solves tau; others wait at the barrier below ----
    if (wid == 0) {
        const int n = cnt;   // >= 1 (max element has v = 0 > -1)
        float lo = -1.0f, hi = 0.0f;
        float tau;

        if (n <= CAP) {
            float v[4];
#pragma unroll
            for (int j = 0; j < 4; ++j) {
                int i = lane + 32 * j;
                v[j] = (i < n) ? abuf[i] : -2.0f;    // sentinel: never in support
            }
#pragma unroll 1
            for (int it = 0; it < NB; ++it) {
                const float tm = 0.5f * (lo + hi);
                float acc = 0.0f;
#pragma unroll
                for (int j = 0; j < 4; ++j) {
                    float d = fmaxf(v[j] - tm, 0.0f);
                    acc = fmaf(d, d, acc);
                }
                if (warp_sum(acc) >= 1.0f) lo = tm; else hi = tm;
            }
            float k = 0.0f, S1 = 0.0f, S2 = 0.0f;
#pragma unroll
            for (int j = 0; j < 4; ++j)
                if (v[j] > lo) { k += 1.0f; S1 += v[j]; S2 = fmaf(v[j], v[j], S2); }
            k = warp_sum(k); S1 = warp_sum(S1); S2 = warp_sum(S2);
            float disc = fmaxf(fmaf(S1, S1, -k * (S2 - 1.0f)), 0.0f);
            tau = (S1 - sqrtf(disc)) / k;
        } else if (n <= ACAP) {
#pragma unroll 1
            for (int it = 0; it < NB; ++it) {
                const float tm = 0.5f * (lo + hi);
                float acc = 0.0f;
                for (int i = lane; i < n; i += 32) {
                    float d = fmaxf(abuf[i] - tm, 0.0f);
                    acc = fmaf(d, d, acc);
                }
                if (warp_sum(acc) >= 1.0f) lo = tm; else hi = tm;
            }
            float k = 0.0f, S1 = 0.0f, S2 = 0.0f;
            for (int i = lane; i < n; i += 32) {
                float v = abuf[i];
                if (v > lo) { k += 1.0f; S1 += v; S2 = fmaf(v, v, S2); }
            }
            k = warp_sum(k); S1 = warp_sum(S1); S2 = warp_sum(S2);
            float disc = fmaxf(fmaf(S1, S1, -k * (S2 - 1.0f)), 0.0f);
            tau = (S1 - sqrtf(disc)) / k;
        } else {
            // pathological: scan the full row in shared
#pragma unroll 1
            for (int it = 0; it < NB; ++it) {
                const float tm = 0.5f * (lo + hi);
                float acc = 0.0f;
                for (int i = lane; i < COLS; i += 32) {
                    float d = fmaxf((zbuf[i] - rmax) - tm, 0.0f);
                    acc = fmaf(d, d, acc);
                }
                if (warp_sum(acc) >= 1.0f) lo = tm; else hi = tm;
            }
            float k = 0.0f, S1 = 0.0f, S2 = 0.0f;
            for (int i = lane; i < COLS; i += 32) {
                float v = zbuf[i] - rmax;
                if (v > lo) { k += 1.0f; S1 += v; S2 = fmaf(v, v, S2); }
            }
            k = warp_sum(k); S1 = warp_sum(S1); S2 = warp_sum(S2);
            float disc = fmaxf(fmaf(S1, S1, -k * (S2 - 1.0f)), 0.0f);
            tau = (S1 - sqrtf(disc)) / k;
        }
        if (lane == 0) sh_tau = tau;
    }
    __syncthreads();
    const float taup = sh_tau + rmax;    // p = max(z - taup, 0)^2

    // ---- Store p from shared ----
#pragma unroll
    for (int c = 0; c < VEC; ++c) {
        const int idx = c * (THREADS * 4) + t * 4;
        float4 zz = *reinterpret_cast<const float4*>(zbuf + idx);
        float d0 = fmaxf(zz.x - taup, 0.0f);
        float d1 = fmaxf(zz.y - taup, 0.0f);
        float d2 = fmaxf(zz.z - taup, 0.0f);
        float d3 = fmaxf(zz.w - taup, 0.0f);
        float4 p;
        p.x = d0*d0; p.y = d1*d1; p.z = d2*d2; p.w = d3*d3;
        __stcs(reinterpret_cast<float4*>(o + idx), p);
    }
}

extern "C" void kernel_launch(void* const* d_in, const int* in_sizes, int n_in,
                              void* d_out, int out_size) {
    const float* scores = (const float*)d_in[0];
    const int*   mask   = (const int*)d_in[1];
    float* out = (float*)d_out;
    const int rows = in_sizes[0] / COLS;
    entmax15_kernel<<<rows, THREADS>>>(scores, mask, out);
}